// round 3
// baseline (speedup 1.0000x reference)
#include <cuda_runtime.h>
#include <cuda_bf16.h>
#include <cstdint>
#include <cstddef>

#define NN 50000
#define NE 1600000
#define HID 64

// ---------------- device scratch (no runtime allocation allowed) ----------------
__device__ float g_insum[(size_t)NN * HID];
__device__ float g_A[(size_t)NN * HID];
__device__ float g_B[(size_t)NN * HID];
__device__ float g_nodemsg[(size_t)NN * HID];
__device__ int   g_count[NN];
__device__ int   g_start[NN + 1];
__device__ int   g_cursor[NN];
__device__ int   g_eid[NE];

// ---------------- CSR build ----------------
__global__ void k_zero_counts() {
    int i = blockIdx.x * blockDim.x + threadIdx.x;
    if (i < NN) g_count[i] = 0;
}

__global__ void k_count(const int* __restrict__ ei) {
    int i = blockIdx.x * blockDim.x + threadIdx.x;
    if (i < NE) atomicAdd(&g_count[ei[i]], 1);
}

__global__ void k_scan() {
    __shared__ int s[1024];
    const int t = threadIdx.x;
    const int chunk = (NN + 1023) / 1024;
    int b = t * chunk;
    int e = b + chunk; if (e > NN) e = NN;
    int sum = 0;
    for (int i = b; i < e && i < NN; i++) sum += g_count[i];
    s[t] = sum;
    __syncthreads();
    for (int off = 1; off < 1024; off <<= 1) {
        int v = (t >= off) ? s[t - off] : 0;
        __syncthreads();
        s[t] += v;
        __syncthreads();
    }
    int run = (t == 0) ? 0 : s[t - 1];
    for (int i = b; i < e && i < NN; i++) {
        int c = g_count[i];
        g_start[i] = run;
        g_cursor[i] = run;
        run += c;
    }
    if (t == 1023) g_start[NN] = run;
}

__global__ void k_fill(const int* __restrict__ ei) {
    int i = blockIdx.x * blockDim.x + threadIdx.x;
    if (i < NE) {
        int p = atomicAdd(&g_cursor[ei[i]], 1);
        g_eid[p] = i;
    }
}

// ---------------- segment sums (gather, no float atomics) ----------------
__global__ void k_insum(const float* __restrict__ eh) {
    int gw = (blockIdx.x * blockDim.x + threadIdx.x) >> 5;
    int lane = threadIdx.x & 31;
    if (gw >= NN) return;
    int s = g_start[gw], e = g_start[gw + 1];
    float2 acc = make_float2(0.f, 0.f);
    for (int j = s; j < e; j++) {
        int eid = g_eid[j];
        float2 v = *((const float2*)(eh + (size_t)eid * HID) + lane);
        acc.x += v.x; acc.y += v.y;
    }
    *((float2*)(g_insum + (size_t)gw * HID) + lane) = acc;
}

__global__ void k_nodemsg(const float* __restrict__ msg) {
    int gw = (blockIdx.x * blockDim.x + threadIdx.x) >> 5;
    int lane = threadIdx.x & 31;
    if (gw >= NN) return;
    int s = g_start[gw], e = g_start[gw + 1];
    float2 acc = make_float2(0.f, 0.f);
    for (int j = s; j < e; j++) {
        int eid = g_eid[j] ^ 1;
        float2 v = *((const float2*)(msg + (size_t)eid * HID) + lane);
        acc.x += v.x; acc.y += v.y;
    }
    *((float2*)(g_nodemsg + (size_t)gw * HID) + lane) = acc;
}

// ---------------- small node GEMMs: A = x@W1^T, B = insum@W2^T + b ----------------
__global__ void __launch_bounds__(128) k_AB(const float* __restrict__ x,
                                            const float* __restrict__ Wm,
                                            const float* __restrict__ bm) {
    __shared__ float s_in[64][68];
    __shared__ float s_W[64][68];
    const int t = threadIdx.x;
    const int base = blockIdx.x * 64;
    const int e0 = (t & 15) * 4;
    const int o0 = (t >> 4) * 8;
    float acc[4][8];

    for (int pass = 0; pass < 2; pass++) {
        const int koff = pass * 64;
        for (int idx = t; idx < 4096; idx += 128) {
            int k = idx & 63, o = idx >> 6;
            s_W[k][o] = Wm[o * 128 + koff + k];
        }
        const float* src = (pass == 0) ? x : g_insum;
        for (int fi = t; fi < 1024; fi += 128) {
            int nl = fi >> 4, kq = fi & 15;
            int n = base + nl;
            float4 v = make_float4(0.f, 0.f, 0.f, 0.f);
            if (n < NN) v = *(const float4*)&src[(size_t)n * HID + kq * 4];
            s_in[kq * 4 + 0][nl] = v.x;
            s_in[kq * 4 + 1][nl] = v.y;
            s_in[kq * 4 + 2][nl] = v.z;
            s_in[kq * 4 + 3][nl] = v.w;
        }
        __syncthreads();

#pragma unroll
        for (int i = 0; i < 4; i++)
#pragma unroll
            for (int j = 0; j < 8; j++) acc[i][j] = 0.f;

        for (int k = 0; k < 64; k++) {
            float4 a = *(float4*)&s_in[k][e0];
            float4 b0 = *(float4*)&s_W[k][o0];
            float4 b1 = *(float4*)&s_W[k][o0 + 4];
            float av[4] = {a.x, a.y, a.z, a.w};
            float bv[8] = {b0.x, b0.y, b0.z, b0.w, b1.x, b1.y, b1.z, b1.w};
#pragma unroll
            for (int i = 0; i < 4; i++)
#pragma unroll
                for (int j = 0; j < 8; j++) acc[i][j] += av[i] * bv[j];
        }

        float bb[8];
        if (pass == 1) {
#pragma unroll
            for (int j = 0; j < 8; j++) bb[j] = bm[o0 + j];
        } else {
#pragma unroll
            for (int j = 0; j < 8; j++) bb[j] = 0.f;
        }
        float* dst = (pass == 0) ? g_A : g_B;
#pragma unroll
        for (int i = 0; i < 4; i++) {
            int n = base + e0 + i;
            if (n < NN) {
                float4 r0 = make_float4(acc[i][0] + bb[0], acc[i][1] + bb[1],
                                        acc[i][2] + bb[2], acc[i][3] + bb[3]);
                float4 r1 = make_float4(acc[i][4] + bb[4], acc[i][5] + bb[5],
                                        acc[i][6] + bb[6], acc[i][7] + bb[7]);
                *(float4*)&dst[(size_t)n * HID + o0] = r0;
                *(float4*)&dst[(size_t)n * HID + o0 + 4] = r1;
            }
        }
        __syncthreads();
    }
}

// ================= mma.sync heavy kernel =================
// Q = eh@W2^T via bf16 3-term split on HMMA (portable tensor-core path),
// messages[m] = relu(A[row[m]]+B[col[m]] - Q[m^1]), Q exchange via smem stage.

__device__ __forceinline__ void mma16816(float* d, const uint32_t* a, const uint32_t* b) {
    asm volatile(
        "mma.sync.aligned.m16n8k16.row.col.f32.bf16.bf16.f32 "
        "{%0,%1,%2,%3}, {%4,%5,%6,%7}, {%8,%9}, {%0,%1,%2,%3};"
        : "+f"(d[0]), "+f"(d[1]), "+f"(d[2]), "+f"(d[3])
        : "r"(a[0]), "r"(a[1]), "r"(a[2]), "r"(a[3]), "r"(b[0]), "r"(b[1]));
}

__device__ __forceinline__ uint32_t pk(__nv_bfloat16 a, __nv_bfloat16 b) {
    return (uint32_t)__bfloat16_as_ushort(a) | ((uint32_t)__bfloat16_as_ushort(b) << 16);
}

// byte strides for bf16 tiles (68 bf16 = 136B -> 2-bank row shift, low conflicts)
#define EHB 136
// fp32 stage stride (68 floats = 272B; 16B-aligned rows, conflict-free in quad phases)
#define STF 68

#define SM_EHI 0
#define SM_ELO (128 * EHB)
#define SM_WHI (256 * EHB)
#define SM_WLO (256 * EHB + 64 * EHB)
#define SM_MSG_TOTAL (256 * EHB + 128 * EHB)

__global__ void __launch_bounds__(128) k_msg_mma(const float* __restrict__ eh,
                                                 const int* __restrict__ ei,
                                                 const float* __restrict__ Wm,
                                                 float* __restrict__ msg) {
    extern __shared__ char sm[];
    char* ehi = sm + SM_EHI;
    char* elo = sm + SM_ELO;
    char* whi = sm + SM_WHI;
    char* wlo = sm + SM_WLO;
    float* stage = (float*)sm;  // reuses EHI+ELO region after MMA phase

    const int t = threadIdx.x;
    const int w = t >> 5;
    const int lane = t & 31;
    const int gid = lane >> 2;   // 0..7
    const int qid = lane & 3;    // 0..3
    const int base = blockIdx.x * 128;

    // ---- load + split eh row t: 64 floats -> hi/lo bf16 ----
    {
        const float4* src = (const float4*)(eh + (size_t)(base + t) * HID);
        char* dh = ehi + t * EHB;
        char* dl = elo + t * EHB;
#pragma unroll
        for (int i = 0; i < 16; i++) {
            float4 v = src[i];
            __nv_bfloat16 h0 = __float2bfloat16_rn(v.x);
            __nv_bfloat16 h1 = __float2bfloat16_rn(v.y);
            __nv_bfloat16 h2 = __float2bfloat16_rn(v.z);
            __nv_bfloat16 h3 = __float2bfloat16_rn(v.w);
            __nv_bfloat16 l0 = __float2bfloat16_rn(v.x - __bfloat162float(h0));
            __nv_bfloat16 l1 = __float2bfloat16_rn(v.y - __bfloat162float(h1));
            __nv_bfloat16 l2 = __float2bfloat16_rn(v.z - __bfloat162float(h2));
            __nv_bfloat16 l3 = __float2bfloat16_rn(v.w - __bfloat162float(h3));
            *(uint2*)(dh + i * 8) = make_uint2(pk(h0, h1), pk(h2, h3));
            *(uint2*)(dl + i * 8) = make_uint2(pk(l0, l1), pk(l2, l3));
        }
    }
    // ---- load + split W2: W2[o][k] = Wm[o*128 + 64 + k] ----
    {
        int o = t >> 1, kb = (t & 1) * 32;
        const float4* src = (const float4*)(Wm + o * 128 + 64 + kb);
        char* dh = whi + o * EHB + kb * 2;
        char* dl = wlo + o * EHB + kb * 2;
#pragma unroll
        for (int i = 0; i < 8; i++) {
            float4 v = src[i];
            __nv_bfloat16 h0 = __float2bfloat16_rn(v.x);
            __nv_bfloat16 h1 = __float2bfloat16_rn(v.y);
            __nv_bfloat16 h2 = __float2bfloat16_rn(v.z);
            __nv_bfloat16 h3 = __float2bfloat16_rn(v.w);
            __nv_bfloat16 l0 = __float2bfloat16_rn(v.x - __bfloat162float(h0));
            __nv_bfloat16 l1 = __float2bfloat16_rn(v.y - __bfloat162float(h1));
            __nv_bfloat16 l2 = __float2bfloat16_rn(v.z - __bfloat162float(h2));
            __nv_bfloat16 l3 = __float2bfloat16_rn(v.w - __bfloat162float(h3));
            *(uint2*)(dh + i * 8) = make_uint2(pk(h0, h1), pk(h2, h3));
            *(uint2*)(dl + i * 8) = make_uint2(pk(l0, l1), pk(l2, l3));
        }
    }
    __syncthreads();

    // ---- MMA mainloop: warp handles rows [w*32, w*32+32), all 64 cols ----
    float acc[2][8][4];
#pragma unroll
    for (int mt = 0; mt < 2; mt++)
#pragma unroll
        for (int nt = 0; nt < 8; nt++)
#pragma unroll
            for (int r = 0; r < 4; r++) acc[mt][nt][r] = 0.f;

#pragma unroll
    for (int ks = 0; ks < 4; ks++) {
        const int k0 = ks * 16;
        uint32_t Ah[2][4], Al[2][4];
#pragma unroll
        for (int mt = 0; mt < 2; mt++) {
            int r0 = w * 32 + mt * 16 + gid;
            const char* ph = ehi + r0 * EHB + (k0 + qid * 2) * 2;
            const char* pl = elo + r0 * EHB + (k0 + qid * 2) * 2;
            Ah[mt][0] = *(const uint32_t*)(ph);
            Ah[mt][1] = *(const uint32_t*)(ph + 8 * EHB);
            Ah[mt][2] = *(const uint32_t*)(ph + 16);
            Ah[mt][3] = *(const uint32_t*)(ph + 8 * EHB + 16);
            Al[mt][0] = *(const uint32_t*)(pl);
            Al[mt][1] = *(const uint32_t*)(pl + 8 * EHB);
            Al[mt][2] = *(const uint32_t*)(pl + 16);
            Al[mt][3] = *(const uint32_t*)(pl + 8 * EHB + 16);
        }
        uint32_t Bh[8][2], Bl[8][2];
#pragma unroll
        for (int nt = 0; nt < 8; nt++) {
            int n = nt * 8 + gid;
            const char* ph = whi + n * EHB + (k0 + qid * 2) * 2;
            const char* pl = wlo + n * EHB + (k0 + qid * 2) * 2;
            Bh[nt][0] = *(const uint32_t*)(ph);
            Bh[nt][1] = *(const uint32_t*)(ph + 16);
            Bl[nt][0] = *(const uint32_t*)(pl);
            Bl[nt][1] = *(const uint32_t*)(pl + 16);
        }
#pragma unroll
        for (int mt = 0; mt < 2; mt++)
#pragma unroll
            for (int nt = 0; nt < 8; nt++) {
                mma16816(acc[mt][nt], Ah[mt], Bh[nt]);
                mma16816(acc[mt][nt], Ah[mt], Bl[nt]);
                mma16816(acc[mt][nt], Al[mt], Bh[nt]);
            }
    }

    __syncthreads();  // done reading eh tiles; reuse as fp32 stage

    // ---- stage Q to smem in row-major [128][STF] ----
#pragma unroll
    for (int mt = 0; mt < 2; mt++) {
        int r0 = w * 32 + mt * 16 + gid;
#pragma unroll
        for (int nt = 0; nt < 8; nt++) {
            int col = nt * 8 + qid * 2;
            *(float2*)(stage + r0 * STF + col) = make_float2(acc[mt][nt][0], acc[mt][nt][1]);
            *(float2*)(stage + (r0 + 8) * STF + col) = make_float2(acc[mt][nt][2], acc[mt][nt][3]);
        }
    }
    __syncthreads();

    // ---- epilogue: thread t -> edge base+t; Q of reverse edge = stage row t^1 ----
    {
        const size_t ge = (size_t)base + t;
        const int r = ei[ge];
        const int c = ei[(size_t)NE + ge];
        const float* q = stage + (t ^ 1) * STF;
        const float4* Ar = (const float4*)(g_A + (size_t)r * HID);
        const float4* Bc = (const float4*)(g_B + (size_t)c * HID);
        float4* dst = (float4*)(msg + ge * HID);
#pragma unroll
        for (int i = 0; i < 16; i++) {
            float4 a = Ar[i];
            float4 b = Bc[i];
            float4 qv = *(const float4*)(q + 4 * i);
            float o0 = a.x + b.x - qv.x;
            float o1 = a.y + b.y - qv.y;
            float o2 = a.z + b.z - qv.z;
            float o3 = a.w + b.w - qv.w;
            o0 = o0 > 0.f ? o0 : 0.f;
            o1 = o1 > 0.f ? o1 : 0.f;
            o2 = o2 > 0.f ? o2 : 0.f;
            o3 = o3 > 0.f ? o3 : 0.f;
            dst[i] = make_float4(o0, o1, o2, o3);
        }
    }
}

// ---------------- x_out = relu([x, node_msg] @ Wn^T + bn) ----------------
__global__ void __launch_bounds__(128) k_xout(const float* __restrict__ x,
                                              const float* __restrict__ Wn,
                                              const float* __restrict__ bn,
                                              float* __restrict__ xout) {
    __shared__ float s_in[64][68];
    __shared__ float s_W[64][68];
    const int t = threadIdx.x;
    const int base = blockIdx.x * 64;
    const int e0 = (t & 15) * 4;
    const int o0 = (t >> 4) * 8;
    float acc[4][8];
#pragma unroll
    for (int i = 0; i < 4; i++)
#pragma unroll
        for (int j = 0; j < 8; j++) acc[i][j] = 0.f;

    for (int pass = 0; pass < 2; pass++) {
        const int koff = pass * 64;
        for (int idx = t; idx < 4096; idx += 128) {
            int k = idx & 63, o = idx >> 6;
            s_W[k][o] = Wn[o * 128 + koff + k];
        }
        const float* src = (pass == 0) ? x : g_nodemsg;
        for (int fi = t; fi < 1024; fi += 128) {
            int nl = fi >> 4, kq = fi & 15;
            int n = base + nl;
            float4 v = make_float4(0.f, 0.f, 0.f, 0.f);
            if (n < NN) v = *(const float4*)&src[(size_t)n * HID + kq * 4];
            s_in[kq * 4 + 0][nl] = v.x;
            s_in[kq * 4 + 1][nl] = v.y;
            s_in[kq * 4 + 2][nl] = v.z;
            s_in[kq * 4 + 3][nl] = v.w;
        }
        __syncthreads();
        for (int k = 0; k < 64; k++) {
            float4 a = *(float4*)&s_in[k][e0];
            float4 b0 = *(float4*)&s_W[k][o0];
            float4 b1 = *(float4*)&s_W[k][o0 + 4];
            float av[4] = {a.x, a.y, a.z, a.w};
            float bv[8] = {b0.x, b0.y, b0.z, b0.w, b1.x, b1.y, b1.z, b1.w};
#pragma unroll
            for (int i = 0; i < 4; i++)
#pragma unroll
                for (int j = 0; j < 8; j++) acc[i][j] += av[i] * bv[j];
        }
        __syncthreads();
    }

    float bb[8];
#pragma unroll
    for (int j = 0; j < 8; j++) bb[j] = bn[o0 + j];
#pragma unroll
    for (int i = 0; i < 4; i++) {
        int n = base + e0 + i;
        if (n < NN) {
            float o[8];
#pragma unroll
            for (int j = 0; j < 8; j++) {
                float v = acc[i][j] + bb[j];
                o[j] = v > 0.f ? v : 0.f;
            }
            *(float4*)&xout[(size_t)n * HID + o0] = make_float4(o[0], o[1], o[2], o[3]);
            *(float4*)&xout[(size_t)n * HID + o0 + 4] = make_float4(o[4], o[5], o[6], o[7]);
        }
    }
}

// ---------------- launch ----------------
extern "C" void kernel_launch(void* const* d_in, const int* in_sizes, int n_in,
                              void* d_out, int out_size) {
    const float* x  = (const float*)d_in[0];
    const int*   ei = (const int*)d_in[1];
    const float* eh = (const float*)d_in[2];
    const float* Wm = (const float*)d_in[3];
    const float* bm = (const float*)d_in[4];
    const float* Wn = (const float*)d_in[5];
    const float* bn = (const float*)d_in[6];
    float* xout = (float*)d_out;
    float* msg  = (float*)d_out + (size_t)NN * HID;

    cudaFuncSetAttribute(k_msg_mma, cudaFuncAttributeMaxDynamicSharedMemorySize, SM_MSG_TOTAL);

    k_zero_counts<<<(NN + 255) / 256, 256>>>();
    k_count<<<(NE + 255) / 256, 256>>>(ei);
    k_scan<<<1, 1024>>>();
    k_fill<<<(NE + 255) / 256, 256>>>(ei);
    k_insum<<<(NN * 32 + 255) / 256, 256>>>(eh);       // one warp per node
    k_AB<<<(NN + 63) / 64, 128>>>(x, Wm, bm);
    k_msg_mma<<<NE / 128, 128, SM_MSG_TOTAL>>>(eh, ei, Wm, msg);
    k_nodemsg<<<(NN * 32 + 255) / 256, 256>>>(msg);    // one warp per node
    k_xout<<<(NN + 63) / 64, 128>>>(x, Wn, bn, xout);
}

// round 4
// speedup vs baseline: 1.4124x; 1.4124x over previous
#include <cuda_runtime.h>
#include <cuda_bf16.h>
#include <cstdint>
#include <cstddef>

#define NN 50000
#define NE 1600000
#define HID 64

// ---------------- device scratch (no runtime allocation allowed) ----------------
__device__ float g_insum[(size_t)NN * HID];
__device__ float g_A[(size_t)NN * HID];
__device__ float g_B[(size_t)NN * HID];
__device__ float g_nodemsg[(size_t)NN * HID];
__device__ int   g_count[NN];
__device__ int   g_start[NN + 1];
__device__ int   g_cursor[NN];
__device__ int   g_eid[NE];

// ---------------- packed fp32x2 helpers (Blackwell base ISA, PTX 8.6 sm_100+) ----
__device__ __forceinline__ uint64_t splat2(float x) {
    uint64_t r;
    asm("mov.b64 %0, {%1, %1};" : "=l"(r) : "f"(x));
    return r;
}
__device__ __forceinline__ void fma2(uint64_t& d, uint64_t a, uint64_t b) {
    asm("fma.rn.f32x2 %0, %1, %2, %0;" : "+l"(d) : "l"(a), "l"(b));
}
__device__ __forceinline__ float2 unpk2(uint64_t v) {
    float2 f;
    asm("mov.b64 {%0, %1}, %2;" : "=f"(f.x), "=f"(f.y) : "l"(v));
    return f;
}

// ---------------- CSR build ----------------
__global__ void k_zero_counts() {
    int i = blockIdx.x * blockDim.x + threadIdx.x;
    if (i < NN) g_count[i] = 0;
}

__global__ void k_count(const int* __restrict__ ei) {
    int i = blockIdx.x * blockDim.x + threadIdx.x;
    if (i < NE) atomicAdd(&g_count[ei[i]], 1);
}

__global__ void k_scan() {
    __shared__ int s[1024];
    const int t = threadIdx.x;
    const int chunk = (NN + 1023) / 1024;
    int b = t * chunk;
    int e = b + chunk; if (e > NN) e = NN;
    int sum = 0;
    for (int i = b; i < e && i < NN; i++) sum += g_count[i];
    s[t] = sum;
    __syncthreads();
    for (int off = 1; off < 1024; off <<= 1) {
        int v = (t >= off) ? s[t - off] : 0;
        __syncthreads();
        s[t] += v;
        __syncthreads();
    }
    int run = (t == 0) ? 0 : s[t - 1];
    for (int i = b; i < e && i < NN; i++) {
        int c = g_count[i];
        g_start[i] = run;
        g_cursor[i] = run;
        run += c;
    }
    if (t == 1023) g_start[NN] = run;
}

__global__ void k_fill(const int* __restrict__ ei) {
    int i = blockIdx.x * blockDim.x + threadIdx.x;
    if (i < NE) {
        int p = atomicAdd(&g_cursor[ei[i]], 1);
        g_eid[p] = i;
    }
}

// ---------------- segment sums (gather, no float atomics) ----------------
__global__ void k_insum(const float* __restrict__ eh) {
    int gw = (blockIdx.x * blockDim.x + threadIdx.x) >> 5;
    int lane = threadIdx.x & 31;
    if (gw >= NN) return;
    int s = g_start[gw], e = g_start[gw + 1];
    float2 acc = make_float2(0.f, 0.f);
    int j = s;
    for (; j + 1 < e; j += 2) {
        int e0 = g_eid[j], e1 = g_eid[j + 1];
        float2 v0 = *((const float2*)(eh + (size_t)e0 * HID) + lane);
        float2 v1 = *((const float2*)(eh + (size_t)e1 * HID) + lane);
        acc.x += v0.x + v1.x;
        acc.y += v0.y + v1.y;
    }
    if (j < e) {
        int e0 = g_eid[j];
        float2 v0 = *((const float2*)(eh + (size_t)e0 * HID) + lane);
        acc.x += v0.x;
        acc.y += v0.y;
    }
    *((float2*)(g_insum + (size_t)gw * HID) + lane) = acc;
}

__global__ void k_nodemsg(const float* __restrict__ msg) {
    int gw = (blockIdx.x * blockDim.x + threadIdx.x) >> 5;
    int lane = threadIdx.x & 31;
    if (gw >= NN) return;
    int s = g_start[gw], e = g_start[gw + 1];
    float2 acc = make_float2(0.f, 0.f);
    int j = s;
    for (; j + 1 < e; j += 2) {
        int e0 = g_eid[j] ^ 1, e1 = g_eid[j + 1] ^ 1;
        float2 v0 = *((const float2*)(msg + (size_t)e0 * HID) + lane);
        float2 v1 = *((const float2*)(msg + (size_t)e1 * HID) + lane);
        acc.x += v0.x + v1.x;
        acc.y += v0.y + v1.y;
    }
    if (j < e) {
        int e0 = g_eid[j] ^ 1;
        float2 v0 = *((const float2*)(msg + (size_t)e0 * HID) + lane);
        acc.x += v0.x;
        acc.y += v0.y;
    }
    *((float2*)(g_nodemsg + (size_t)gw * HID) + lane) = acc;
}

// ---------------- small node GEMMs: A = x@W1^T, B = insum@W2^T + b ----------------
// 64-node x 64-out tile, 128 threads, thread tile 4n x 8o, fp32x2 packed FMA
__global__ void __launch_bounds__(128) k_AB(const float* __restrict__ x,
                                            const float* __restrict__ Wm,
                                            const float* __restrict__ bm) {
    __shared__ float s_in[64][68];
    __shared__ float s_W[64][68];
    const int t = threadIdx.x;
    const int base = blockIdx.x * 64;
    const int e0 = (t & 15) * 4;
    const int o0 = (t >> 4) * 8;

    for (int pass = 0; pass < 2; pass++) {
        const int koff = pass * 64;
        for (int idx = t; idx < 4096; idx += 128) {
            int k = idx & 63, o = idx >> 6;
            s_W[k][o] = Wm[o * 128 + koff + k];
        }
        const float* src = (pass == 0) ? x : g_insum;
        for (int fi = t; fi < 1024; fi += 128) {
            int nl = fi >> 4, kq = fi & 15;
            int n = base + nl;
            float4 v = make_float4(0.f, 0.f, 0.f, 0.f);
            if (n < NN) v = *(const float4*)&src[(size_t)n * HID + kq * 4];
            s_in[kq * 4 + 0][nl] = v.x;
            s_in[kq * 4 + 1][nl] = v.y;
            s_in[kq * 4 + 2][nl] = v.z;
            s_in[kq * 4 + 3][nl] = v.w;
        }
        __syncthreads();

        uint64_t acc2[4][4];
#pragma unroll
        for (int i = 0; i < 4; i++)
#pragma unroll
            for (int j = 0; j < 4; j++) acc2[i][j] = 0ULL;

#pragma unroll 4
        for (int k = 0; k < 64; k++) {
            float4 a = *(float4*)&s_in[k][e0];
            const uint64_t* bp = (const uint64_t*)&s_W[k][o0];
            uint64_t b0 = bp[0], b1 = bp[1], b2 = bp[2], b3 = bp[3];
            uint64_t s0 = splat2(a.x), s1 = splat2(a.y), s2 = splat2(a.z), s3 = splat2(a.w);
            fma2(acc2[0][0], s0, b0); fma2(acc2[0][1], s0, b1); fma2(acc2[0][2], s0, b2); fma2(acc2[0][3], s0, b3);
            fma2(acc2[1][0], s1, b0); fma2(acc2[1][1], s1, b1); fma2(acc2[1][2], s1, b2); fma2(acc2[1][3], s1, b3);
            fma2(acc2[2][0], s2, b0); fma2(acc2[2][1], s2, b1); fma2(acc2[2][2], s2, b2); fma2(acc2[2][3], s2, b3);
            fma2(acc2[3][0], s3, b0); fma2(acc2[3][1], s3, b1); fma2(acc2[3][2], s3, b2); fma2(acc2[3][3], s3, b3);
        }

        float bb[8];
        if (pass == 1) {
#pragma unroll
            for (int j = 0; j < 8; j++) bb[j] = bm[o0 + j];
        } else {
#pragma unroll
            for (int j = 0; j < 8; j++) bb[j] = 0.f;
        }
        float* dst = (pass == 0) ? g_A : g_B;
#pragma unroll
        for (int i = 0; i < 4; i++) {
            int n = base + e0 + i;
            if (n < NN) {
                float2 p0 = unpk2(acc2[i][0]);
                float2 p1 = unpk2(acc2[i][1]);
                float2 p2 = unpk2(acc2[i][2]);
                float2 p3 = unpk2(acc2[i][3]);
                float4 r0 = make_float4(p0.x + bb[0], p0.y + bb[1], p1.x + bb[2], p1.y + bb[3]);
                float4 r1 = make_float4(p2.x + bb[4], p2.y + bb[5], p3.x + bb[6], p3.y + bb[7]);
                *(float4*)&dst[(size_t)n * HID + o0] = r0;
                *(float4*)&dst[(size_t)n * HID + o0 + 4] = r1;
            }
        }
        __syncthreads();
    }
}

// ---------------- heavy kernel: Q = eh@W2^T, messages = relu(A[row]+B[col]-Q[rev]) ----------------
__global__ void __launch_bounds__(128) k_msg(const float* __restrict__ eh,
                                             const int* __restrict__ ei,
                                             const float* __restrict__ Wm,
                                             float* __restrict__ msg) {
    __shared__ float s_eh[64][68];
    __shared__ float s_W[64][68];
    __shared__ int s_row[64];
    __shared__ int s_col[64];
    const int t = threadIdx.x;
    const int base = blockIdx.x * 64;

    // W2 tile
    for (int idx = t; idx < 4096; idx += 128) {
        int k = idx & 63, o = idx >> 6;
        s_W[k][o] = Wm[o * 128 + 64 + k];
    }
    // eh tile, transposed [k][e]
    for (int fi = t; fi < 1024; fi += 128) {
        int el = fi >> 4, kq = fi & 15;
        float4 v = *(const float4*)&eh[(size_t)(base + el) * HID + kq * 4];
        s_eh[kq * 4 + 0][el] = v.x;
        s_eh[kq * 4 + 1][el] = v.y;
        s_eh[kq * 4 + 2][el] = v.z;
        s_eh[kq * 4 + 3][el] = v.w;
    }
    if (t < 64) {
        s_row[t] = ei[base + t];
        s_col[t] = ei[NE + base + t];
    }
    __syncthreads();

    const int e0 = (t & 15) * 4;
    const int o0 = (t >> 4) * 8;
    uint64_t acc2[4][4];
#pragma unroll
    for (int i = 0; i < 4; i++)
#pragma unroll
        for (int j = 0; j < 4; j++) acc2[i][j] = 0ULL;

#pragma unroll 4
    for (int k = 0; k < 64; k++) {
        float4 a = *(float4*)&s_eh[k][e0];
        const uint64_t* bp = (const uint64_t*)&s_W[k][o0];
        uint64_t b0 = bp[0], b1 = bp[1], b2 = bp[2], b3 = bp[3];
        uint64_t s0 = splat2(a.x), s1 = splat2(a.y), s2 = splat2(a.z), s3 = splat2(a.w);
        fma2(acc2[0][0], s0, b0); fma2(acc2[0][1], s0, b1); fma2(acc2[0][2], s0, b2); fma2(acc2[0][3], s0, b3);
        fma2(acc2[1][0], s1, b0); fma2(acc2[1][1], s1, b1); fma2(acc2[1][2], s1, b2); fma2(acc2[1][3], s1, b3);
        fma2(acc2[2][0], s2, b0); fma2(acc2[2][1], s2, b1); fma2(acc2[2][2], s2, b2); fma2(acc2[2][3], s2, b3);
        fma2(acc2[3][0], s3, b0); fma2(acc2[3][1], s3, b1); fma2(acc2[3][2], s3, b2); fma2(acc2[3][3], s3, b3);
    }

    // epilogue: pairs (e0,e0+1),(e0+2,e0+3) are reverse pairs; Q of reverse is acc row i^1
#pragma unroll
    for (int i = 0; i < 4; i++) {
        int el = e0 + i;
        size_t ge = (size_t)(base + el);
        int r = s_row[el];
        int c = s_col[el];
        const float* Ar = g_A + (size_t)r * HID + o0;
        const float* Bc = g_B + (size_t)c * HID + o0;
        float4 a0 = *(const float4*)Ar;
        float4 a1 = *(const float4*)(Ar + 4);
        float4 b0 = *(const float4*)Bc;
        float4 b1 = *(const float4*)(Bc + 4);
        int p = i ^ 1;
        float2 q0 = unpk2(acc2[p][0]);
        float2 q1 = unpk2(acc2[p][1]);
        float2 q2 = unpk2(acc2[p][2]);
        float2 q3 = unpk2(acc2[p][3]);
        float out[8];
        out[0] = a0.x + b0.x - q0.x;
        out[1] = a0.y + b0.y - q0.y;
        out[2] = a0.z + b0.z - q1.x;
        out[3] = a0.w + b0.w - q1.y;
        out[4] = a1.x + b1.x - q2.x;
        out[5] = a1.y + b1.y - q2.y;
        out[6] = a1.z + b1.z - q3.x;
        out[7] = a1.w + b1.w - q3.y;
#pragma unroll
        for (int j = 0; j < 8; j++) out[j] = out[j] > 0.f ? out[j] : 0.f;
        *(float4*)&msg[ge * HID + o0] = make_float4(out[0], out[1], out[2], out[3]);
        *(float4*)&msg[ge * HID + o0 + 4] = make_float4(out[4], out[5], out[6], out[7]);
    }
}

// ---------------- x_out = relu([x, node_msg] @ Wn^T + bn) ----------------
__global__ void __launch_bounds__(128) k_xout(const float* __restrict__ x,
                                              const float* __restrict__ Wn,
                                              const float* __restrict__ bn,
                                              float* __restrict__ xout) {
    __shared__ float s_in[64][68];
    __shared__ float s_W[64][68];
    const int t = threadIdx.x;
    const int base = blockIdx.x * 64;
    const int e0 = (t & 15) * 4;
    const int o0 = (t >> 4) * 8;
    uint64_t acc2[4][4];
#pragma unroll
    for (int i = 0; i < 4; i++)
#pragma unroll
        for (int j = 0; j < 4; j++) acc2[i][j] = 0ULL;

    for (int pass = 0; pass < 2; pass++) {
        const int koff = pass * 64;
        for (int idx = t; idx < 4096; idx += 128) {
            int k = idx & 63, o = idx >> 6;
            s_W[k][o] = Wn[o * 128 + koff + k];
        }
        const float* src = (pass == 0) ? x : g_nodemsg;
        for (int fi = t; fi < 1024; fi += 128) {
            int nl = fi >> 4, kq = fi & 15;
            int n = base + nl;
            float4 v = make_float4(0.f, 0.f, 0.f, 0.f);
            if (n < NN) v = *(const float4*)&src[(size_t)n * HID + kq * 4];
            s_in[kq * 4 + 0][nl] = v.x;
            s_in[kq * 4 + 1][nl] = v.y;
            s_in[kq * 4 + 2][nl] = v.z;
            s_in[kq * 4 + 3][nl] = v.w;
        }
        __syncthreads();
#pragma unroll 4
        for (int k = 0; k < 64; k++) {
            float4 a = *(float4*)&s_in[k][e0];
            const uint64_t* bp = (const uint64_t*)&s_W[k][o0];
            uint64_t b0 = bp[0], b1 = bp[1], b2 = bp[2], b3 = bp[3];
            uint64_t s0 = splat2(a.x), s1 = splat2(a.y), s2 = splat2(a.z), s3 = splat2(a.w);
            fma2(acc2[0][0], s0, b0); fma2(acc2[0][1], s0, b1); fma2(acc2[0][2], s0, b2); fma2(acc2[0][3], s0, b3);
            fma2(acc2[1][0], s1, b0); fma2(acc2[1][1], s1, b1); fma2(acc2[1][2], s1, b2); fma2(acc2[1][3], s1, b3);
            fma2(acc2[2][0], s2, b0); fma2(acc2[2][1], s2, b1); fma2(acc2[2][2], s2, b2); fma2(acc2[2][3], s2, b3);
            fma2(acc2[3][0], s3, b0); fma2(acc2[3][1], s3, b1); fma2(acc2[3][2], s3, b2); fma2(acc2[3][3], s3, b3);
        }
        __syncthreads();
    }

    float bb[8];
#pragma unroll
    for (int j = 0; j < 8; j++) bb[j] = bn[o0 + j];
#pragma unroll
    for (int i = 0; i < 4; i++) {
        int n = base + e0 + i;
        if (n < NN) {
            float2 p0 = unpk2(acc2[i][0]);
            float2 p1 = unpk2(acc2[i][1]);
            float2 p2 = unpk2(acc2[i][2]);
            float2 p3 = unpk2(acc2[i][3]);
            float o[8] = {p0.x + bb[0], p0.y + bb[1], p1.x + bb[2], p1.y + bb[3],
                          p2.x + bb[4], p2.y + bb[5], p3.x + bb[6], p3.y + bb[7]};
#pragma unroll
            for (int j = 0; j < 8; j++) o[j] = o[j] > 0.f ? o[j] : 0.f;
            *(float4*)&xout[(size_t)n * HID + o0] = make_float4(o[0], o[1], o[2], o[3]);
            *(float4*)&xout[(size_t)n * HID + o0 + 4] = make_float4(o[4], o[5], o[6], o[7]);
        }
    }
}

// ---------------- launch ----------------
extern "C" void kernel_launch(void* const* d_in, const int* in_sizes, int n_in,
                              void* d_out, int out_size) {
    const float* x  = (const float*)d_in[0];
    const int*   ei = (const int*)d_in[1];
    const float* eh = (const float*)d_in[2];
    const float* Wm = (const float*)d_in[3];
    const float* bm = (const float*)d_in[4];
    const float* Wn = (const float*)d_in[5];
    const float* bn = (const float*)d_in[6];
    float* xout = (float*)d_out;
    float* msg  = (float*)d_out + (size_t)NN * HID;

    k_zero_counts<<<(NN + 255) / 256, 256>>>();
    k_count<<<(NE + 255) / 256, 256>>>(ei);
    k_scan<<<1, 1024>>>();
    k_fill<<<(NE + 255) / 256, 256>>>(ei);
    k_insum<<<(NN * 32 + 255) / 256, 256>>>(eh);       // one warp per node
    k_AB<<<(NN + 63) / 64, 128>>>(x, Wm, bm);
    k_msg<<<NE / 64, 128>>>(eh, ei, Wm, msg);
    k_nodemsg<<<(NN * 32 + 255) / 256, 256>>>(msg);    // one warp per node
    k_xout<<<(NN + 63) / 64, 128>>>(x, Wn, bn, xout);
}